// round 8
// baseline (speedup 1.0000x reference)
#include <cuda_runtime.h>

// DilateAttention: B=8, C=384 (12 heads x 32), H=W=56, kernel 3x3, dilation 2, pad 2.
// q,k,v: [B, C, H, W] f32. out: [B, H, W, C] f32.
//
// R8: warp-per-row + shuffle window sharing.
//  - One warp handles one image row: lanes 0..27 = 28 pixel-pairs (2 px/lane).
//  - Per (channel, row) each lane loads ONE center float2; the left/right
//    dilated windows come from __shfl_up/down(1) (exact within a row).
//  - Image-edge windows are exactly the shfl-invalid lanes: fix by zeroing
//    those 6 logits once after K accumulation, and zeroing the corresponding
//    softmax weights before V (reference: OOB neighbor value is 0).
//  - Output staged per channel-chunk in smem, stored cooperatively (32B/4B
//    coalesced float4s) instead of 1536B-stride scatter.

#define HD     32
#define HEADS  12
#define WD     56
#define HT     56
#define BD     8
#define HW     (WD * HT)
#define CTOT   384
#define NTHR   256
#define PXB    448           // pixels per block: 8 warps x 56
#define PITCH  8

__global__ __launch_bounds__(NTHR, 4)
void dilate_attn_kernel(const float* __restrict__ q,
                        const float* __restrict__ k,
                        const float* __restrict__ v,
                        float* __restrict__ out)
{
    __shared__ __align__(16) float stage[PXB * PITCH];  // 14.3 KB
    __shared__ int sOb[PXB];                            // 1.8 KB

    const int tid  = threadIdx.x;
    const int w    = tid >> 5;
    const int lane = tid & 31;
    const int xg   = (lane < 28) ? lane : 27;   // lanes 28-31 duplicate xg=27
    const bool act = (lane < 28);
    const int y    = blockIdx.x * 8 + w;
    const int head = blockIdx.y;
    const int b    = blockIdx.z;
    const int x0   = xg * 2;

    const int base = (b * CTOT + head * HD) * HW;
    const int pix  = y * WD + x0;
    const int pxl  = w * 56 + x0;               // pixel index within block

    if (act) {
        int ob = ((b * HT + y) * WD + x0) * CTOT + head * HD;
        sOb[pxl]     = ob;
        sOb[pxl + 1] = ob + CTOT;
    }

    const bool yT = (y >= 2);
    const bool yB = (y <= HT - 3);

    const float* qc = q + base + pix;
    const float* kc = k + base + pix;
    const float* vc = v + base + pix;

    float a0[9], a1[9];
#pragma unroll
    for (int p = 0; p < 9; p++) { a0[p] = 0.0f; a1[p] = 0.0f; }

    // ================= K phase: logits =================
#pragma unroll
    for (int ch = 0; ch < 4; ch++) {
        float2 qv[8];
#pragma unroll
        for (int c = 0; c < 8; c++)
            qv[c] = *(const float2*)(qc + (ch * 8 + c) * HW);

        // row y-2 -> windows 0,1,2
        if (yT) {
#pragma unroll
            for (int c = 0; c < 8; c++) {
                float2 C = *(const float2*)(kc + (ch * 8 + c) * HW - 2 * WD);
                float Lx = __shfl_up_sync(0xffffffffu, C.x, 1);
                float Ly = __shfl_up_sync(0xffffffffu, C.y, 1);
                float Rx = __shfl_down_sync(0xffffffffu, C.x, 1);
                float Ry = __shfl_down_sync(0xffffffffu, C.y, 1);
                a0[0] = fmaf(qv[c].x, Lx,  a0[0]); a1[0] = fmaf(qv[c].y, Ly,  a1[0]);
                a0[1] = fmaf(qv[c].x, C.x, a0[1]); a1[1] = fmaf(qv[c].y, C.y, a1[1]);
                a0[2] = fmaf(qv[c].x, Rx,  a0[2]); a1[2] = fmaf(qv[c].y, Ry,  a1[2]);
            }
        }
        // row y -> windows 3,4,5
        {
#pragma unroll
            for (int c = 0; c < 8; c++) {
                float2 C = *(const float2*)(kc + (ch * 8 + c) * HW);
                float Lx = __shfl_up_sync(0xffffffffu, C.x, 1);
                float Ly = __shfl_up_sync(0xffffffffu, C.y, 1);
                float Rx = __shfl_down_sync(0xffffffffu, C.x, 1);
                float Ry = __shfl_down_sync(0xffffffffu, C.y, 1);
                a0[3] = fmaf(qv[c].x, Lx,  a0[3]); a1[3] = fmaf(qv[c].y, Ly,  a1[3]);
                a0[4] = fmaf(qv[c].x, C.x, a0[4]); a1[4] = fmaf(qv[c].y, C.y, a1[4]);
                a0[5] = fmaf(qv[c].x, Rx,  a0[5]); a1[5] = fmaf(qv[c].y, Ry,  a1[5]);
            }
        }
        // row y+2 -> windows 6,7,8
        if (yB) {
#pragma unroll
            for (int c = 0; c < 8; c++) {
                float2 C = *(const float2*)(kc + (ch * 8 + c) * HW + 2 * WD);
                float Lx = __shfl_up_sync(0xffffffffu, C.x, 1);
                float Ly = __shfl_up_sync(0xffffffffu, C.y, 1);
                float Rx = __shfl_down_sync(0xffffffffu, C.x, 1);
                float Ry = __shfl_down_sync(0xffffffffu, C.y, 1);
                a0[6] = fmaf(qv[c].x, Lx,  a0[6]); a1[6] = fmaf(qv[c].y, Ly,  a1[6]);
                a0[7] = fmaf(qv[c].x, C.x, a0[7]); a1[7] = fmaf(qv[c].y, C.y, a1[7]);
                a0[8] = fmaf(qv[c].x, Rx,  a0[8]); a1[8] = fmaf(qv[c].y, Ry,  a1[8]);
            }
        }
    }

    // edge-column fixup: both pixels of pair 0 / pair 27 have OOB left/right
    if (xg == 0)  { a0[0] = a0[3] = a0[6] = 0.0f; a1[0] = a1[3] = a1[6] = 0.0f; }
    if (xg == 27) { a0[2] = a0[5] = a0[8] = 0.0f; a1[2] = a1[5] = a1[8] = 0.0f; }

    // ================= softmax (normalization folded into weights) =================
    {
        const float scale = 0.17677669529663687f;  // 32^-0.5
        float m0 = -1e30f, m1 = -1e30f;
#pragma unroll
        for (int p = 0; p < 9; p++) {
            a0[p] *= scale; a1[p] *= scale;
            m0 = fmaxf(m0, a0[p]); m1 = fmaxf(m1, a1[p]);
        }
        float d0 = 0.0f, d1 = 0.0f;
#pragma unroll
        for (int p = 0; p < 9; p++) {
            a0[p] = __expf(a0[p] - m0); d0 += a0[p];
            a1[p] = __expf(a1[p] - m1); d1 += a1[p];
        }
        float i0 = 1.0f / d0, i1 = 1.0f / d1;
#pragma unroll
        for (int p = 0; p < 9; p++) { a0[p] *= i0; a1[p] *= i1; }
    }

    // zero weights of OOB windows for the V phase (reference: w * 0)
    if (xg == 0)  { a0[0] = a0[3] = a0[6] = 0.0f; a1[0] = a1[3] = a1[6] = 0.0f; }
    if (xg == 27) { a0[2] = a0[5] = a0[8] = 0.0f; a1[2] = a1[5] = a1[8] = 0.0f; }

    // ================= V phase: weighted sum, staged stores =================
#pragma unroll
    for (int ch = 0; ch < 4; ch++) {
        float acc0[8], acc1[8];
#pragma unroll
        for (int c = 0; c < 8; c++) { acc0[c] = 0.0f; acc1[c] = 0.0f; }

        if (yT) {
#pragma unroll
            for (int c = 0; c < 8; c++) {
                float2 C = *(const float2*)(vc + (ch * 8 + c) * HW - 2 * WD);
                float Lx = __shfl_up_sync(0xffffffffu, C.x, 1);
                float Ly = __shfl_up_sync(0xffffffffu, C.y, 1);
                float Rx = __shfl_down_sync(0xffffffffu, C.x, 1);
                float Ry = __shfl_down_sync(0xffffffffu, C.y, 1);
                acc0[c] = fmaf(a0[0], Lx, fmaf(a0[1], C.x, fmaf(a0[2], Rx, acc0[c])));
                acc1[c] = fmaf(a1[0], Ly, fmaf(a1[1], C.y, fmaf(a1[2], Ry, acc1[c])));
            }
        }
        {
#pragma unroll
            for (int c = 0; c < 8; c++) {
                float2 C = *(const float2*)(vc + (ch * 8 + c) * HW);
                float Lx = __shfl_up_sync(0xffffffffu, C.x, 1);
                float Ly = __shfl_up_sync(0xffffffffu, C.y, 1);
                float Rx = __shfl_down_sync(0xffffffffu, C.x, 1);
                float Ry = __shfl_down_sync(0xffffffffu, C.y, 1);
                acc0[c] = fmaf(a0[3], Lx, fmaf(a0[4], C.x, fmaf(a0[5], Rx, acc0[c])));
                acc1[c] = fmaf(a1[3], Ly, fmaf(a1[4], C.y, fmaf(a1[5], Ry, acc1[c])));
            }
        }
        if (yB) {
#pragma unroll
            for (int c = 0; c < 8; c++) {
                float2 C = *(const float2*)(vc + (ch * 8 + c) * HW + 2 * WD);
                float Lx = __shfl_up_sync(0xffffffffu, C.x, 1);
                float Ly = __shfl_up_sync(0xffffffffu, C.y, 1);
                float Rx = __shfl_down_sync(0xffffffffu, C.x, 1);
                float Ry = __shfl_down_sync(0xffffffffu, C.y, 1);
                acc0[c] = fmaf(a0[6], Lx, fmaf(a0[7], C.x, fmaf(a0[8], Rx, acc0[c])));
                acc1[c] = fmaf(a1[6], Ly, fmaf(a1[7], C.y, fmaf(a1[8], Ry, acc1[c])));
            }
        }

        if (act) {
            float* st = &stage[pxl * PITCH];
            *(float4*)(st)              = make_float4(acc0[0], acc0[1], acc0[2], acc0[3]);
            *(float4*)(st + 4)          = make_float4(acc0[4], acc0[5], acc0[6], acc0[7]);
            *(float4*)(st + PITCH)      = make_float4(acc1[0], acc1[1], acc1[2], acc1[3]);
            *(float4*)(st + PITCH + 4)  = make_float4(acc1[4], acc1[5], acc1[6], acc1[7]);
        }
        __syncthreads();

        // cooperative store of this chunk: 448 px x 32B
#pragma unroll
        for (int j = 0; j < 4; j++) {
            int idx = tid + NTHR * j;           // 0..1023
            if (idx < PXB * 2) {
                int px = idx >> 1;
                int ci = (idx & 1) << 2;
                float4 val = *(const float4*)&stage[px * PITCH + ci];
                *(float4*)(out + sOb[px] + ch * 8 + ci) = val;
            }
        }
        __syncthreads();
    }
}

extern "C" void kernel_launch(void* const* d_in, const int* in_sizes, int n_in,
                              void* d_out, int out_size)
{
    const float* q = (const float*)d_in[0];
    const float* k = (const float*)d_in[1];
    const float* v = (const float*)d_in[2];
    float* out = (float*)d_out;

    dim3 grid(HT / 8, HEADS, BD);   // 7 x 12 x 8 = 672 blocks
    dilate_attn_kernel<<<grid, NTHR>>>(q, k, v, out);
}

// round 9
// speedup vs baseline: 1.0011x; 1.0011x over previous
#include <cuda_runtime.h>

// DilateAttention: B=8, C=384 (12 heads x 32), H=W=56, kernel 3x3, dilation 2, pad 2.
// q,k,v: [B, C, H, W] f32. out: [B, H, W, C] f32.
//
// R9 = R7 (2 px/thread, float2 window loads, guarded neighbor skip) with the
// register working set cut via channel chunks of 4 (CC=4) so that
// __launch_bounds__(256,5) holds without spills -> 62.5% occupancy (R7: 41.8%).
// scale (32^-0.5) is folded into q at load time. OOB windows are skipped ->
// logit stays exactly 0, matching unfold's zero padding.

#define HD     32
#define HEADS  12
#define WD     56
#define HT     56
#define BD     8
#define HW     (WD * HT)
#define CTOT   384
#define XG     28          // x-pairs per row
#define NTHR   256
#define CC     4
#define NCH    (HD / CC)   // 8

__global__ __launch_bounds__(NTHR, 5)
void dilate_attn_kernel(const float* __restrict__ q,
                        const float* __restrict__ k,
                        const float* __restrict__ v,
                        float* __restrict__ out)
{
    const int gid  = blockIdx.x * NTHR + threadIdx.x;
    const int xg   = gid % XG;
    int r1         = gid / XG;
    const int y    = r1 % HT;
    int r2         = r1 / HT;
    const int head = r2 % HEADS;
    const int b    = r2 / HEADS;
    const int x0   = xg * 2;

    const int base = (b * CTOT + head * HD) * HW;
    const int pix  = y * WD + x0;

    const bool cL = (x0 >= 2);
    const bool cR = (x0 <= WD - 4);
    const bool yT = (y >= 2);
    const bool yB = (y <= HT - 3);

    const bool vmask[9] = {
        yT && cL, yT, yT && cR,
        cL,       true, cR,
        yB && cL, yB, yB && cR
    };
    const int voff[9] = {
        -2 * WD - 2, -2 * WD, -2 * WD + 2,
        -2,           0,       2,
         2 * WD - 2,  2 * WD,  2 * WD + 2
    };

    const float* qc = q + base + pix;
    const float* kc = k + base + pix;
    const float* vc = v + base + pix;

    const float scale = 0.17677669529663687f;  // 32^-0.5

    float a0[9], a1[9];
#pragma unroll
    for (int p = 0; p < 9; p++) { a0[p] = 0.0f; a1[p] = 0.0f; }

    // ================= K phase: logits, channel chunks of 4 =================
#pragma unroll
    for (int ch = 0; ch < NCH; ch++) {
        float2 qv[CC];
#pragma unroll
        for (int c = 0; c < CC; c++) {
            qv[c] = *(const float2*)(qc + (ch * CC + c) * HW);
            qv[c].x *= scale; qv[c].y *= scale;   // fold softmax scale into q
        }

#pragma unroll
        for (int p = 0; p < 9; p++) {
            if (vmask[p]) {
                const float* kp = kc + ch * CC * HW + voff[p];
                float s0 = a0[p], s1 = a1[p];
#pragma unroll
                for (int c = 0; c < CC; c++) {
                    float2 kv = *(const float2*)(kp + c * HW);
                    s0 = fmaf(qv[c].x, kv.x, s0);
                    s1 = fmaf(qv[c].y, kv.y, s1);
                }
                a0[p] = s0; a1[p] = s1;
            }
        }
    }

    // ================= softmax (normalization folded into weights) =================
    {
        float m0 = -1e30f, m1 = -1e30f;
#pragma unroll
        for (int p = 0; p < 9; p++) { m0 = fmaxf(m0, a0[p]); m1 = fmaxf(m1, a1[p]); }
        float d0 = 0.0f, d1 = 0.0f;
#pragma unroll
        for (int p = 0; p < 9; p++) {
            a0[p] = __expf(a0[p] - m0); d0 += a0[p];
            a1[p] = __expf(a1[p] - m1); d1 += a1[p];
        }
        float i0 = 1.0f / d0, i1 = 1.0f / d1;
#pragma unroll
        for (int p = 0; p < 9; p++) { a0[p] *= i0; a1[p] *= i1; }
    }

    // ================= V phase: weighted sum + direct stores =================
    const int ob = ((b * HT + y) * WD + x0) * CTOT + head * HD;

#pragma unroll
    for (int ch = 0; ch < NCH; ch++) {
        float acc0[CC], acc1[CC];
#pragma unroll
        for (int c = 0; c < CC; c++) { acc0[c] = 0.0f; acc1[c] = 0.0f; }

#pragma unroll
        for (int p = 0; p < 9; p++) {
            if (vmask[p]) {
                const float w0 = a0[p], w1 = a1[p];
                const float* vp = vc + ch * CC * HW + voff[p];
#pragma unroll
                for (int c = 0; c < CC; c++) {
                    float2 vv = *(const float2*)(vp + c * HW);
                    acc0[c] = fmaf(w0, vv.x, acc0[c]);
                    acc1[c] = fmaf(w1, vv.y, acc1[c]);
                }
            }
        }

        float* o0 = out + ob + ch * CC;
        *(float4*)(o0)        = make_float4(acc0[0], acc0[1], acc0[2], acc0[3]);
        *(float4*)(o0 + CTOT) = make_float4(acc1[0], acc1[1], acc1[2], acc1[3]);
    }
}

extern "C" void kernel_launch(void* const* d_in, const int* in_sizes, int n_in,
                              void* d_out, int out_size)
{
    const float* q = (const float*)d_in[0];
    const float* k = (const float*)d_in[1];
    const float* v = (const float*)d_in[2];
    float* out = (float*)d_out;

    int total  = BD * HEADS * HT * XG;   // 150528 threads (2 px each)
    int blocks = total / NTHR;           // 588
    dilate_attn_kernel<<<blocks, NTHR>>>(q, k, v, out);
}